// round 14
// baseline (speedup 1.0000x reference)
#include <cuda_runtime.h>
#include <cuda_bf16.h>
#include <cuda_fp16.h>
#include <cstdint>

// ---------------- problem constants ----------------
#define BS      8
#define NQ      900
#define EMBED   256
#define HEADS   8
#define LEVELS  4
#define POINTS  4
#define NV      13294
#define NBQ     (BS * NQ)      // 7200
#define KDIM    256
#define MV      (BS * NV)      // 106352
#define MVPAD   (831 * 128)    // 106368

__device__ __constant__ int c_LH[4] = {100, 50, 25, 13};
__device__ __constant__ int c_LW[4] = {100, 50, 25, 13};
__device__ __constant__ int c_LS[4] = {0, 10000, 12500, 13125};

// ---------------- scratch ----------------
__device__ __half g_vh[(size_t)MV * EMBED];        // projected value (GEMM output)
__device__ __half g_valh[(size_t)MVPAD * EMBED];   // fp16 copy of input value (GEMM A)
__device__ float g_qa[(size_t)NBQ * 384];
__device__ float g_attn[(size_t)NBQ * EMBED];
__device__ float g_bias_qa[384];

__device__ __half g_Bvh[256 * 256], g_Bvl[256 * 256];
__device__ __half g_Bqh[384 * 256], g_Bql[384 * 256];
__device__ __half g_Buh[256 * 256], g_Bul[256 * 256];

// ---------------- helpers ----------------
__device__ __forceinline__ uint32_t smem_u32(const void* p) {
    uint32_t a;
    asm("{ .reg .u64 t; cvta.to.shared.u64 t, %1; cvt.u32.u64 %0, t; }" : "=r"(a) : "l"(p));
    return a;
}
__device__ __forceinline__ uint32_t pack_h2(float x, float y) {
    __half2 h = __floats2half2_rn(x, y);
    return *reinterpret_cast<uint32_t*>(&h);
}
__device__ __forceinline__ void mma_f16(float d[4],
                                        uint32_t a0, uint32_t a1, uint32_t a2, uint32_t a3,
                                        uint32_t b0, uint32_t b1) {
    asm volatile(
        "mma.sync.aligned.m16n8k16.row.col.f32.f16.f16.f32 "
        "{%0,%1,%2,%3}, {%4,%5,%6,%7}, {%8,%9}, {%0,%1,%2,%3};"
        : "+f"(d[0]), "+f"(d[1]), "+f"(d[2]), "+f"(d[3])
        : "r"(a0), "r"(a1), "r"(a2), "r"(a3), "r"(b0), "r"(b1));
}
__device__ __forceinline__ void ldsm_x4(uint32_t& r0, uint32_t& r1, uint32_t& r2, uint32_t& r3,
                                        uint32_t addr) {
    asm volatile("ldmatrix.sync.aligned.m8n8.x4.shared.b16 {%0,%1,%2,%3}, [%4];"
                 : "=r"(r0), "=r"(r1), "=r"(r2), "=r"(r3) : "r"(addr));
}
__device__ __forceinline__ void cp_async16(uint32_t saddr, const void* gaddr) {
    asm volatile("cp.async.ca.shared.global [%0], [%1], 16;" :: "r"(saddr), "l"(gaddr));
}

// ---------------- weight conversion kernels ----------------
__device__ __forceinline__ void conv_one(const float* __restrict__ W,
                                         __half* __restrict__ Bh,
                                         __half* __restrict__ Bl,
                                         int N, int j, int nbase) {
    int k = j / N, n = j % N;
    float x = W[j];
    __half hb = __float2half_rn(x);
    float lo = x - __half2float(hb);
    Bh[(size_t)(nbase + n) * KDIM + k] = hb;
    Bl[(size_t)(nbase + n) * KDIM + k] = __float2half_rn(lo);
}

__global__ void conv_v_kernel(const float* __restrict__ Wv) {
    int i = blockIdx.x * 256 + threadIdx.x;
    if (i < 65536) conv_one(Wv, g_Bvh, g_Bvl, 256, i, 0);
}

__global__ void conv_rest_kernel(const float* __restrict__ Woff,
                                 const float* __restrict__ Wattn,
                                 const float* __restrict__ Wout,
                                 const float* __restrict__ b_off,
                                 const float* __restrict__ b_attn) {
    int i = blockIdx.x * 256 + threadIdx.x;
    if (i < 65536)        conv_one(Woff,  g_Bqh, g_Bql, 256, i, 0);
    else if (i < 98304)   conv_one(Wattn, g_Bqh, g_Bql, 128, i - 65536, 256);
    else if (i < 163840)  conv_one(Wout,  g_Buh, g_Bul, 256, i - 98304, 0);
    else if (i < 164224) {
        int j2 = i - 163840;
        g_bias_qa[j2] = (j2 < 256) ? b_off[j2] : b_attn[j2 - 256];
    }
}

// ---------------- value fp32 -> fp16 streaming conversion -------------------
__global__ void conv_value_kernel(const float* __restrict__ value) {
    const size_t total = (size_t)MV * EMBED;        // 27,226,112
    size_t i = ((size_t)blockIdx.x * 256 + threadIdx.x) * 8;
    if (i >= (size_t)MVPAD * EMBED) return;
    uint4 o;
    if (i < total) {
        float4 f0 = *reinterpret_cast<const float4*>(value + i);
        float4 f1 = *reinterpret_cast<const float4*>(value + i + 4);
        o.x = pack_h2(f0.x, f0.y); o.y = pack_h2(f0.z, f0.w);
        o.z = pack_h2(f1.x, f1.y); o.w = pack_h2(f1.z, f1.w);
    } else {
        o = make_uint4(0u, 0u, 0u, 0u);
    }
    *reinterpret_cast<uint4*>(g_valh + i) = o;
}

// ---------------- GEMM constants ----------------
#define KC 32
#define ROWB 80

// ---------------- pure cp.async fp16-A GEMM (value projection) --------------
// C[M,256] = A[Mpad,256] @ B[256,256]^T + bias, output fp16.
template<int BN, int OCC>
__global__ __launch_bounds__(256, OCC)
void mma_gemm_f16a_kernel(const __half* __restrict__ A,
                          const __half* __restrict__ Bh,
                          const float* __restrict__ bias,
                          __half* __restrict__ Ch,
                          int M, int Ntot)
{
    constexpr int A_B   = 0;
    constexpr int B_B   = 128 * ROWB;
    constexpr int STAGE = (128 + BN) * ROWB;
    constexpr int NTC   = BN / 16;

    extern __shared__ char smemc[];
    __shared__ float s_bias[BN];

    const int tid = threadIdx.x;
    const int wid = tid >> 5;
    const int lane = tid & 31;
    const int g = lane >> 2;
    const int tig = lane & 3;
    const int wm = wid & 3;
    const int wn = wid >> 2;
    const int m0 = blockIdx.y * 128;
    const int n0 = blockIdx.x * BN;

    if (tid < BN) s_bias[tid] = bias[n0 + tid];
    const uint32_t sbase = smem_u32(smemc);

    float acc[2][NTC][4];
#pragma unroll
    for (int mt = 0; mt < 2; mt++)
#pragma unroll
        for (int nt = 0; nt < NTC; nt++)
#pragma unroll
            for (int q = 0; q < 4; q++) acc[mt][nt][q] = 0.f;

    const int lm_arow = lane & 15;
    const int lm_akoff = (lane >> 4) * 16;
    const int lm_brow = (lane & 7) + ((lane >> 4) << 3);
    const int lm_bkoff = ((lane >> 3) & 1) * 16;

    auto issue = [&](int stage, int k0) {
        const uint32_t Sb = sbase + stage * STAGE;
#pragma unroll
        for (int u = tid; u < 512; u += 256) {          // A: 128 rows x 64B
            const int row = u >> 2, c = u & 3;
            cp_async16(Sb + A_B + row * ROWB + c * 16,
                       A + (size_t)(m0 + row) * KDIM + k0 + c * 8);
        }
#pragma unroll
        for (int u = tid; u < BN * 4; u += 256) {       // B: BN rows x 64B
            const int row = u >> 2, c = u & 3;
            cp_async16(Sb + B_B + row * ROWB + c * 16,
                       Bh + (size_t)(n0 + row) * KDIM + k0 + c * 8);
        }
        asm volatile("cp.async.commit_group;" ::: "memory");
    };

    issue(0, 0);
    asm volatile("cp.async.wait_group 0;" ::: "memory");
    __syncthreads();

    int buf = 0;
    const int ntiles = KDIM / KC;
    for (int kt = 0; kt < ntiles; kt++) {
        const bool more = (kt + 1 < ntiles);
        if (more) issue(buf ^ 1, (kt + 1) * KC);

        const uint32_t Sb = sbase + buf * STAGE;
#pragma unroll
        for (int kk = 0; kk < 2; kk++) {
            uint32_t bh[NTC][2];
#pragma unroll
            for (int p = 0; p < NTC / 2; p++) {
                const uint32_t baddr = Sb + (uint32_t)((wn * (BN / 2) + p * 16 + lm_brow) * ROWB + kk * 32 + lm_bkoff);
                ldsm_x4(bh[2 * p][0], bh[2 * p][1], bh[2 * p + 1][0], bh[2 * p + 1][1],
                        baddr + B_B);
            }
            uint32_t ah[2][4];
#pragma unroll
            for (int mt = 0; mt < 2; mt++) {
                const uint32_t aaddr = Sb + (uint32_t)((wm * 32 + mt * 16 + lm_arow) * ROWB + kk * 32 + lm_akoff);
                ldsm_x4(ah[mt][0], ah[mt][1], ah[mt][2], ah[mt][3], aaddr + A_B);
            }
#pragma unroll
            for (int mt = 0; mt < 2; mt++)
#pragma unroll
                for (int nt = 0; nt < NTC; nt++)
                    mma_f16(acc[mt][nt], ah[mt][0], ah[mt][1], ah[mt][2], ah[mt][3],
                            bh[nt][0], bh[nt][1]);
        }

        if (more) {
            asm volatile("cp.async.wait_group 0;" ::: "memory");
            __syncthreads();
            buf ^= 1;
        }
    }

    // ---- epilogue (fp16 out) ----
#pragma unroll
    for (int mt = 0; mt < 2; mt++) {
        const int r0 = m0 + wm * 32 + mt * 16 + g;
        const int r1 = r0 + 8;
#pragma unroll
        for (int nt = 0; nt < NTC; nt++) {
            const int cloc = wn * (BN / 2) + nt * 8 + tig * 2;
            const int col = n0 + cloc;
            const float b0 = s_bias[cloc], b1 = s_bias[cloc + 1];
            if (r0 < M)
                *reinterpret_cast<__half2*>(&Ch[(size_t)r0 * Ntot + col]) =
                    __floats2half2_rn(acc[mt][nt][0] + b0, acc[mt][nt][1] + b1);
            if (r1 < M)
                *reinterpret_cast<__half2*>(&Ch[(size_t)r1 * Ntot + col]) =
                    __floats2half2_rn(acc[mt][nt][2] + b0, acc[mt][nt][3] + b1);
        }
    }
}

// ---------------- fp32-A HMMA GEMM (qa + out projections) -------------------
template<int TERMS, int BN, int OCC>
__global__ __launch_bounds__(256, OCC)
void mma_gemm_kernel(const float* __restrict__ A,
                     const __half* __restrict__ Bh,
                     const __half* __restrict__ Bl,
                     const float* __restrict__ bias,
                     const float* __restrict__ resid,
                     float* __restrict__ C,
                     __half* __restrict__ Ch,
                     int M, int Ntot)
{
    constexpr int A_B    = 0;
    constexpr int B_HI_B = 128 * ROWB;
    constexpr int B_LO_B = B_HI_B + BN * ROWB;
    constexpr int STAGE  = B_HI_B + TERMS * BN * ROWB;
    constexpr int NTC    = BN / 16;

    extern __shared__ char smemc[];
    __shared__ float s_bias[BN];

    const int tid = threadIdx.x;
    const int wid = tid >> 5;
    const int lane = tid & 31;
    const int g = lane >> 2;
    const int tig = lane & 3;
    const int wm = wid & 3;
    const int wn = wid >> 2;
    const int m0 = blockIdx.y * 128;
    const int n0 = blockIdx.x * BN;

    if (tid < BN) s_bias[tid] = bias[n0 + tid];

    const uint32_t sbase = smem_u32(smemc);

    float acc[2][NTC][4];
#pragma unroll
    for (int mt = 0; mt < 2; mt++)
#pragma unroll
        for (int nt = 0; nt < NTC; nt++)
#pragma unroll
            for (int q = 0; q < 4; q++) acc[mt][nt][q] = 0.f;

    const int a_row[4] = { (tid + 0) >> 3, (tid + 256) >> 3, (tid + 512) >> 3, (tid + 768) >> 3 };
    const int a_q = tid & 7;

    const int lm_arow = lane & 15;
    const int lm_akoff = (lane >> 4) * 16;
    const int lm_brow = (lane & 7) + ((lane >> 4) << 3);
    const int lm_bkoff = ((lane >> 3) & 1) * 16;

    auto fill_A = [&](int stage, const float4* pa) {
#pragma unroll
        for (int i = 0; i < 4; i++) {
            const float4 f = pa[i];
            const uint32_t off = (uint32_t)(a_row[i] * ROWB + a_q * 8);
            *reinterpret_cast<uint2*>(smemc + stage * STAGE + A_B + off) =
                make_uint2(pack_h2(f.x, f.y), pack_h2(f.z, f.w));
        }
    };

    auto issue_B = [&](int stage, int k0) {
        const uint32_t Sb = sbase + stage * STAGE;
#pragma unroll
        for (int u = tid; u < BN * 4; u += 256) {
            const int row = u >> 2, c = u & 3;
            cp_async16(Sb + B_HI_B + row * ROWB + c * 16,
                       Bh + (size_t)(n0 + row) * KDIM + k0 + c * 8);
            if (TERMS == 2)
                cp_async16(Sb + B_LO_B + row * ROWB + c * 16,
                           Bl + (size_t)(n0 + row) * KDIM + k0 + c * 8);
        }
        asm volatile("cp.async.commit_group;" ::: "memory");
    };

    {
        issue_B(0, 0);
        float4 pa[4];
#pragma unroll
        for (int i = 0; i < 4; i++) {
            pa[i] = make_float4(0.f, 0.f, 0.f, 0.f);
            if (m0 + a_row[i] < M)
                pa[i] = *reinterpret_cast<const float4*>(&A[(size_t)(m0 + a_row[i]) * KDIM + a_q * 4]);
        }
        fill_A(0, pa);
        asm volatile("cp.async.wait_group 0;" ::: "memory");
    }
    __syncthreads();

    const int ntiles = KDIM / KC;
    int buf = 0;

    for (int kt = 0; kt < ntiles; kt++) {
        const bool more = (kt + 1 < ntiles);
        float4 pa[4];
        if (more) {
            const int k0 = (kt + 1) * KC;
            issue_B(buf ^ 1, k0);
#pragma unroll
            for (int i = 0; i < 4; i++) {
                pa[i] = make_float4(0.f, 0.f, 0.f, 0.f);
                if (m0 + a_row[i] < M)
                    pa[i] = *reinterpret_cast<const float4*>(&A[(size_t)(m0 + a_row[i]) * KDIM + k0 + a_q * 4]);
            }
        }

        const uint32_t Sb = sbase + buf * STAGE;
#pragma unroll
        for (int kk = 0; kk < 2; kk++) {
            uint32_t bh[NTC][2], bl[NTC][2];
#pragma unroll
            for (int p = 0; p < NTC / 2; p++) {
                const uint32_t baddr = Sb + (uint32_t)((wn * (BN / 2) + p * 16 + lm_brow) * ROWB + kk * 32 + lm_bkoff);
                ldsm_x4(bh[2 * p][0], bh[2 * p][1], bh[2 * p + 1][0], bh[2 * p + 1][1],
                        baddr + B_HI_B);
                if (TERMS == 2)
                    ldsm_x4(bl[2 * p][0], bl[2 * p][1], bl[2 * p + 1][0], bl[2 * p + 1][1],
                            baddr + B_LO_B);
            }
            uint32_t ah[2][4];
#pragma unroll
            for (int mt = 0; mt < 2; mt++) {
                const uint32_t aaddr = Sb + (uint32_t)((wm * 32 + mt * 16 + lm_arow) * ROWB + kk * 32 + lm_akoff);
                ldsm_x4(ah[mt][0], ah[mt][1], ah[mt][2], ah[mt][3], aaddr + A_B);
            }
#pragma unroll
            for (int mt = 0; mt < 2; mt++)
#pragma unroll
                for (int nt = 0; nt < NTC; nt++) {
                    mma_f16(acc[mt][nt], ah[mt][0], ah[mt][1], ah[mt][2], ah[mt][3],
                            bh[nt][0], bh[nt][1]);
                    if (TERMS == 2)
                        mma_f16(acc[mt][nt], ah[mt][0], ah[mt][1], ah[mt][2], ah[mt][3],
                                bl[nt][0], bl[nt][1]);
                }
        }

        if (more) {
            fill_A(buf ^ 1, pa);
            asm volatile("cp.async.wait_group 0;" ::: "memory");
            __syncthreads();
            buf ^= 1;
        }
    }

    // ---- epilogue ----
#pragma unroll
    for (int mt = 0; mt < 2; mt++) {
        const int r0 = m0 + wm * 32 + mt * 16 + g;
        const int r1 = r0 + 8;
#pragma unroll
        for (int nt = 0; nt < NTC; nt++) {
            const int cloc = wn * (BN / 2) + nt * 8 + tig * 2;
            const int col = n0 + cloc;
            const float b0 = s_bias[cloc], b1 = s_bias[cloc + 1];
            float2 v0 = make_float2(acc[mt][nt][0] + b0, acc[mt][nt][1] + b1);
            float2 v1 = make_float2(acc[mt][nt][2] + b0, acc[mt][nt][3] + b1);
            if (resid) {
                if (r0 < M) {
                    const float2 rv = *reinterpret_cast<const float2*>(&resid[(size_t)r0 * 256 + col]);
                    v0.x += rv.x; v0.y += rv.y;
                }
                if (r1 < M) {
                    const float2 rv = *reinterpret_cast<const float2*>(&resid[(size_t)r1 * 256 + col]);
                    v1.x += rv.x; v1.y += rv.y;
                }
            }
            if (Ch) {
                if (r0 < M)
                    *reinterpret_cast<__half2*>(&Ch[(size_t)r0 * Ntot + col]) = __floats2half2_rn(v0.x, v0.y);
                if (r1 < M)
                    *reinterpret_cast<__half2*>(&Ch[(size_t)r1 * Ntot + col]) = __floats2half2_rn(v1.x, v1.y);
            } else {
                if (r0 < M) *reinterpret_cast<float2*>(&C[(size_t)r0 * Ntot + col]) = v0;
                if (r1 < M) *reinterpret_cast<float2*>(&C[(size_t)r1 * Ntot + col]) = v1;
            }
        }
    }
}

// ---------------- sampling kernel: 2 queries/block, half2 gathers ----------
__global__ __launch_bounds__(256)
void msda_sample_kernel(const float* __restrict__ rp)
{
    const int tid = threadIdx.x;
    const int qi = tid >> 7;
    const int tq = tid & 127;
    const int q = blockIdx.x * 2 + qi;
    const int b = q / NQ;

    __shared__ float s_aw[2][128];
    __shared__ int   s_pos[2][128][4];
    __shared__ float s_wt[2][128][4];

    s_aw[qi][tq] = g_qa[(size_t)q * 384 + 256 + tq];
    __syncthreads();

    if (tid < 16) {
        const int sq = tid >> 3, h = tid & 7;
        float* aw = &s_aw[sq][h * 16];
        float mx = -1e30f;
#pragma unroll
        for (int i = 0; i < 16; i++) mx = fmaxf(mx, aw[i]);
        float e[16];
        float sum = 0.f;
#pragma unroll
        for (int i = 0; i < 16; i++) { e[i] = __expf(aw[i] - mx); sum += e[i]; }
        float inv = 1.f / sum;
#pragma unroll
        for (int i = 0; i < 16; i++) aw[i] = e[i] * inv;
    }
    __syncthreads();

    {
        const int s = tq;
        const int l = (s >> 2) & 3;
        const float aw = s_aw[qi][s];
        const float offx = g_qa[(size_t)q * 384 + s * 2];
        const float offy = g_qa[(size_t)q * 384 + s * 2 + 1];
        const float rx = rp[((size_t)q * LEVELS + l) * 2];
        const float ry = rp[((size_t)q * LEVELS + l) * 2 + 1];
        const int W = c_LW[l], H = c_LH[l], st = c_LS[l];

        const float locx = rx + offx / (float)W;
        const float locy = ry + offy / (float)H;
        const float x = locx * (float)W - 0.5f;
        const float y = locy * (float)H - 0.5f;
        const float x0f = floorf(x), y0f = floorf(y);
        const float lx = x - x0f, ly = y - y0f;
        const int x0 = (int)x0f, y0 = (int)y0f;

#pragma unroll
        for (int cc = 0; cc < 4; cc++) {
            const int dx = cc & 1, dy = cc >> 1;
            const int xi = x0 + dx, yi = y0 + dy;
            const float wx = dx ? lx : (1.f - lx);
            const float wy = dy ? ly : (1.f - ly);
            const bool valid = (xi >= 0) && (xi < W) && (yi >= 0) && (yi < H);
            const int xc = min(max(xi, 0), W - 1);
            const int yc = min(max(yi, 0), H - 1);
            s_pos[qi][s][cc] = st + yc * W + xc;
            s_wt[qi][s][cc] = valid ? (wx * wy * aw) : 0.f;
        }
    }
    __syncthreads();

    const int h = tq >> 4;
    const int d2 = tq & 15;
    const int ch = h * 32 + d2 * 2;
    const __half* vb = g_vh + (size_t)b * NV * EMBED + ch;
    float2 acc = make_float2(0.f, 0.f);
#pragma unroll
    for (int i = 0; i < 16; i++) {
        const int s = h * 16 + i;
#pragma unroll
        for (int cc = 0; cc < 4; cc++) {
            const float w = s_wt[qi][s][cc];
            const __half2 hv = *reinterpret_cast<const __half2*>(vb + (size_t)s_pos[qi][s][cc] * EMBED);
            const float2 f = __half22float2(hv);
            acc.x = fmaf(w, f.x, acc.x);
            acc.y = fmaf(w, f.y, acc.y);
        }
    }
    *reinterpret_cast<float2*>(&g_attn[(size_t)q * EMBED + ch]) = acc;
}

// ---------------- launch ----------------
extern "C" void kernel_launch(void* const* d_in, const int* in_sizes, int n_in,
                              void* d_out, int out_size)
{
    const float* query  = (const float*)d_in[0];
    const float* value  = (const float*)d_in[1];
    const float* rp     = (const float*)d_in[2];
    const float* W_off  = (const float*)d_in[4];
    const float* b_off  = (const float*)d_in[5];
    const float* W_attn = (const float*)d_in[6];
    const float* b_attn = (const float*)d_in[7];
    const float* W_v    = (const float*)d_in[8];
    const float* b_v    = (const float*)d_in[9];
    const float* W_out  = (const float*)d_in[10];
    const float* b_out  = (const float*)d_in[11];
    float* out = (float*)d_out;

    float *pqa, *pattn, *pbias_qa;
    __half *pvh, *pvalh;
    cudaGetSymbolAddress((void**)&pvh,      g_vh);
    cudaGetSymbolAddress((void**)&pvalh,    g_valh);
    cudaGetSymbolAddress((void**)&pqa,      g_qa);
    cudaGetSymbolAddress((void**)&pattn,    g_attn);
    cudaGetSymbolAddress((void**)&pbias_qa, g_bias_qa);

    __half *bvh, *bvl, *bqh, *bql, *buh, *bul;
    cudaGetSymbolAddress((void**)&bvh, g_Bvh); cudaGetSymbolAddress((void**)&bvl, g_Bvl);
    cudaGetSymbolAddress((void**)&bqh, g_Bqh); cudaGetSymbolAddress((void**)&bql, g_Bql);
    cudaGetSymbolAddress((void**)&buh, g_Buh); cudaGetSymbolAddress((void**)&bul, g_Bul);

    const int DS64  = 2 * ((128 + 2 * 64) * ROWB);    // 40960 (TERMS=2, BN=64)
    const int DSF   = 2 * ((128 + 128) * ROWB);       // 40960 (f16a, BN=128)
    cudaFuncSetAttribute((const void*)mma_gemm_kernel<2, 64, 2>,
                         cudaFuncAttributeMaxDynamicSharedMemorySize, DS64);
    cudaFuncSetAttribute((const void*)mma_gemm_f16a_kernel<128, 2>,
                         cudaFuncAttributeMaxDynamicSharedMemorySize, DSF);

    static cudaStream_t s2 = nullptr;
    static cudaEvent_t evFork = nullptr, evJoin = nullptr;
    if (!s2) {
        cudaStreamCreateWithFlags(&s2, cudaStreamNonBlocking);
        cudaEventCreateWithFlags(&evFork, cudaEventDisableTiming);
        cudaEventCreateWithFlags(&evJoin, cudaEventDisableTiming);
    }

    // fork immediately: value-path on main, query-path on s2
    cudaEventRecord(evFork, 0);
    cudaStreamWaitEvent(s2, evFork, 0);

    // main stream: weight conv + value fp16 conv -> pure cp.async value GEMM
    conv_v_kernel<<<256, 256>>>(W_v);
    conv_value_kernel<<<(MVPAD * EMBED / 8 + 255) / 256, 256>>>(value);
    {
        dim3 grid(2, MVPAD / 128);
        mma_gemm_f16a_kernel<128, 2><<<grid, 256, DSF>>>(pvalh, bvh, b_v, pvh, MV, 256);
    }

    // s2: conv_rest -> fused offsets+logits GEMM (ordered on the SAME stream)
    conv_rest_kernel<<<642, 256, 0, s2>>>(W_off, W_attn, W_out, b_off, b_attn);
    {
        dim3 grid(6, (NBQ + 127) / 128);
        mma_gemm_kernel<2, 64, 2><<<grid, 256, DS64, s2>>>(query, bqh, bql, pbias_qa, nullptr,
                                                           pqa, nullptr, NBQ, 384);
    }

    // join
    cudaEventRecord(evJoin, s2);
    cudaStreamWaitEvent(0, evJoin, 0);

    msda_sample_kernel<<<NBQ / 2, 256>>>(rp);

    {   // output projection + residual: 2-term, BN=64
        dim3 grid(4, (NBQ + 127) / 128);
        mma_gemm_kernel<2, 64, 2><<<grid, 256, DS64>>>(pattn, buh, bul, b_out, query,
                                                       out, nullptr, NBQ, 256);
    }
}

// round 15
// speedup vs baseline: 1.0629x; 1.0629x over previous
#include <cuda_runtime.h>
#include <cuda_bf16.h>
#include <cuda_fp16.h>
#include <cstdint>

// ---------------- problem constants ----------------
#define BS      8
#define NQ      900
#define EMBED   256
#define HEADS   8
#define LEVELS  4
#define POINTS  4
#define NV      13294
#define NBQ     (BS * NQ)      // 7200
#define KDIM    256
#define MV      (BS * NV)      // 106352
#define NCHUNK  4
// tile boundaries covering 2 batches per chunk (ceil(i*2*NV/128))
// t = {0, 208, 416, 624, 831}

__device__ __constant__ int c_LH[4] = {100, 50, 25, 13};
__device__ __constant__ int c_LW[4] = {100, 50, 25, 13};
__device__ __constant__ int c_LS[4] = {0, 10000, 12500, 13125};

// ---------------- scratch ----------------
__device__ __half g_vh[(size_t)MV * EMBED];
__device__ float g_qa[(size_t)NBQ * 384];
__device__ float g_attn[(size_t)NBQ * EMBED];
__device__ float g_bias_qa[384];

__device__ __half g_Bvh[256 * 256], g_Bvl[256 * 256];
__device__ __half g_Bqh[384 * 256], g_Bql[384 * 256];
__device__ __half g_Buh[256 * 256], g_Bul[256 * 256];

// ---------------- helpers ----------------
__device__ __forceinline__ uint32_t smem_u32(const void* p) {
    uint32_t a;
    asm("{ .reg .u64 t; cvta.to.shared.u64 t, %1; cvt.u32.u64 %0, t; }" : "=r"(a) : "l"(p));
    return a;
}
__device__ __forceinline__ uint32_t pack_h2(float x, float y) {
    __half2 h = __floats2half2_rn(x, y);
    return *reinterpret_cast<uint32_t*>(&h);
}
__device__ __forceinline__ void mma_f16(float d[4],
                                        uint32_t a0, uint32_t a1, uint32_t a2, uint32_t a3,
                                        uint32_t b0, uint32_t b1) {
    asm volatile(
        "mma.sync.aligned.m16n8k16.row.col.f32.f16.f16.f32 "
        "{%0,%1,%2,%3}, {%4,%5,%6,%7}, {%8,%9}, {%0,%1,%2,%3};"
        : "+f"(d[0]), "+f"(d[1]), "+f"(d[2]), "+f"(d[3])
        : "r"(a0), "r"(a1), "r"(a2), "r"(a3), "r"(b0), "r"(b1));
}
__device__ __forceinline__ void ldsm_x4(uint32_t& r0, uint32_t& r1, uint32_t& r2, uint32_t& r3,
                                        uint32_t addr) {
    asm volatile("ldmatrix.sync.aligned.m8n8.x4.shared.b16 {%0,%1,%2,%3}, [%4];"
                 : "=r"(r0), "=r"(r1), "=r"(r2), "=r"(r3) : "r"(addr));
}
__device__ __forceinline__ void cp_async16(uint32_t saddr, const void* gaddr) {
    asm volatile("cp.async.ca.shared.global [%0], [%1], 16;" :: "r"(saddr), "l"(gaddr));
}

// ---------------- weight conversion kernels ----------------
__device__ __forceinline__ void conv_one(const float* __restrict__ W,
                                         __half* __restrict__ Bh,
                                         __half* __restrict__ Bl,
                                         int N, int j, int nbase) {
    int k = j / N, n = j % N;
    float x = W[j];
    __half hb = __float2half_rn(x);
    float lo = x - __half2float(hb);
    Bh[(size_t)(nbase + n) * KDIM + k] = hb;
    Bl[(size_t)(nbase + n) * KDIM + k] = __float2half_rn(lo);
}

__global__ void conv_v_kernel(const float* __restrict__ Wv) {
    int i = blockIdx.x * 256 + threadIdx.x;
    if (i < 65536) conv_one(Wv, g_Bvh, g_Bvl, 256, i, 0);
}

__global__ void conv_rest_kernel(const float* __restrict__ Woff,
                                 const float* __restrict__ Wattn,
                                 const float* __restrict__ Wout,
                                 const float* __restrict__ b_off,
                                 const float* __restrict__ b_attn) {
    int i = blockIdx.x * 256 + threadIdx.x;
    if (i < 65536)        conv_one(Woff,  g_Bqh, g_Bql, 256, i, 0);
    else if (i < 98304)   conv_one(Wattn, g_Bqh, g_Bql, 128, i - 65536, 256);
    else if (i < 163840)  conv_one(Wout,  g_Buh, g_Bul, 256, i - 98304, 0);
    else if (i < 164224) {
        int j2 = i - 163840;
        g_bias_qa[j2] = (j2 < 256) ? b_off[j2] : b_attn[j2 - 256];
    }
}

// ---------------- HMMA GEMM: CTA 128xBN, fp16 TERMS-split, fp32 A in-kernel -
#define KC 32
#define ROWB 80

template<int TERMS, int BN, int OCC>
__global__ __launch_bounds__(256, OCC)
void mma_gemm_kernel(const float* __restrict__ A,
                     const __half* __restrict__ Bh,
                     const __half* __restrict__ Bl,
                     const float* __restrict__ bias,
                     const float* __restrict__ resid,
                     float* __restrict__ C,
                     __half* __restrict__ Ch,
                     int M, int Ntot)
{
    constexpr int A_B    = 0;
    constexpr int B_HI_B = 128 * ROWB;
    constexpr int B_LO_B = B_HI_B + BN * ROWB;
    constexpr int STAGE  = B_HI_B + TERMS * BN * ROWB;
    constexpr int NTC    = BN / 16;

    extern __shared__ char smemc[];
    __shared__ float s_bias[BN];

    const int tid = threadIdx.x;
    const int wid = tid >> 5;
    const int lane = tid & 31;
    const int g = lane >> 2;
    const int tig = lane & 3;
    const int wm = wid & 3;
    const int wn = wid >> 2;
    const int m0 = blockIdx.y * 128;
    const int n0 = blockIdx.x * BN;

    if (tid < BN) s_bias[tid] = bias[n0 + tid];

    const uint32_t sbase = smem_u32(smemc);

    float acc[2][NTC][4];
#pragma unroll
    for (int mt = 0; mt < 2; mt++)
#pragma unroll
        for (int nt = 0; nt < NTC; nt++)
#pragma unroll
            for (int q = 0; q < 4; q++) acc[mt][nt][q] = 0.f;

    const int a_row[4] = { (tid + 0) >> 3, (tid + 256) >> 3, (tid + 512) >> 3, (tid + 768) >> 3 };
    const int a_q = tid & 7;

    const int lm_arow = lane & 15;
    const int lm_akoff = (lane >> 4) * 16;
    const int lm_brow = (lane & 7) + ((lane >> 4) << 3);
    const int lm_bkoff = ((lane >> 3) & 1) * 16;

    auto fill_A = [&](int stage, const float4* pa) {
#pragma unroll
        for (int i = 0; i < 4; i++) {
            const float4 f = pa[i];
            const uint32_t off = (uint32_t)(a_row[i] * ROWB + a_q * 8);
            *reinterpret_cast<uint2*>(smemc + stage * STAGE + A_B + off) =
                make_uint2(pack_h2(f.x, f.y), pack_h2(f.z, f.w));
        }
    };

    auto issue_B = [&](int stage, int k0) {
        const uint32_t Sb = sbase + stage * STAGE;
#pragma unroll
        for (int u = tid; u < BN * 4; u += 256) {
            const int row = u >> 2, c = u & 3;
            cp_async16(Sb + B_HI_B + row * ROWB + c * 16,
                       Bh + (size_t)(n0 + row) * KDIM + k0 + c * 8);
            if (TERMS == 2)
                cp_async16(Sb + B_LO_B + row * ROWB + c * 16,
                           Bl + (size_t)(n0 + row) * KDIM + k0 + c * 8);
        }
        asm volatile("cp.async.commit_group;" ::: "memory");
    };

    {
        issue_B(0, 0);
        float4 pa[4];
#pragma unroll
        for (int i = 0; i < 4; i++) {
            pa[i] = make_float4(0.f, 0.f, 0.f, 0.f);
            if (m0 + a_row[i] < M)
                pa[i] = *reinterpret_cast<const float4*>(&A[(size_t)(m0 + a_row[i]) * KDIM + a_q * 4]);
        }
        fill_A(0, pa);
        asm volatile("cp.async.wait_group 0;" ::: "memory");
    }
    __syncthreads();

    const int ntiles = KDIM / KC;
    int buf = 0;

    for (int kt = 0; kt < ntiles; kt++) {
        const bool more = (kt + 1 < ntiles);
        float4 pa[4];
        if (more) {
            const int k0 = (kt + 1) * KC;
            issue_B(buf ^ 1, k0);
#pragma unroll
            for (int i = 0; i < 4; i++) {
                pa[i] = make_float4(0.f, 0.f, 0.f, 0.f);
                if (m0 + a_row[i] < M)
                    pa[i] = *reinterpret_cast<const float4*>(&A[(size_t)(m0 + a_row[i]) * KDIM + k0 + a_q * 4]);
            }
        }

        const uint32_t Sb = sbase + buf * STAGE;
#pragma unroll
        for (int kk = 0; kk < 2; kk++) {
            uint32_t bh[NTC][2], bl[NTC][2];
#pragma unroll
            for (int p = 0; p < NTC / 2; p++) {
                const uint32_t baddr = Sb + (uint32_t)((wn * (BN / 2) + p * 16 + lm_brow) * ROWB + kk * 32 + lm_bkoff);
                ldsm_x4(bh[2 * p][0], bh[2 * p][1], bh[2 * p + 1][0], bh[2 * p + 1][1],
                        baddr + B_HI_B);
                if (TERMS == 2)
                    ldsm_x4(bl[2 * p][0], bl[2 * p][1], bl[2 * p + 1][0], bl[2 * p + 1][1],
                            baddr + B_LO_B);
            }
            uint32_t ah[2][4];
#pragma unroll
            for (int mt = 0; mt < 2; mt++) {
                const uint32_t aaddr = Sb + (uint32_t)((wm * 32 + mt * 16 + lm_arow) * ROWB + kk * 32 + lm_akoff);
                ldsm_x4(ah[mt][0], ah[mt][1], ah[mt][2], ah[mt][3], aaddr + A_B);
            }
#pragma unroll
            for (int mt = 0; mt < 2; mt++)
#pragma unroll
                for (int nt = 0; nt < NTC; nt++) {
                    mma_f16(acc[mt][nt], ah[mt][0], ah[mt][1], ah[mt][2], ah[mt][3],
                            bh[nt][0], bh[nt][1]);
                    if (TERMS == 2)
                        mma_f16(acc[mt][nt], ah[mt][0], ah[mt][1], ah[mt][2], ah[mt][3],
                                bl[nt][0], bl[nt][1]);
                }
        }

        if (more) {
            fill_A(buf ^ 1, pa);
            asm volatile("cp.async.wait_group 0;" ::: "memory");
            __syncthreads();
            buf ^= 1;
        }
    }

    // ---- epilogue ----
#pragma unroll
    for (int mt = 0; mt < 2; mt++) {
        const int r0 = m0 + wm * 32 + mt * 16 + g;
        const int r1 = r0 + 8;
#pragma unroll
        for (int nt = 0; nt < NTC; nt++) {
            const int cloc = wn * (BN / 2) + nt * 8 + tig * 2;
            const int col = n0 + cloc;
            const float b0 = s_bias[cloc], b1 = s_bias[cloc + 1];
            float2 v0 = make_float2(acc[mt][nt][0] + b0, acc[mt][nt][1] + b1);
            float2 v1 = make_float2(acc[mt][nt][2] + b0, acc[mt][nt][3] + b1);
            if (resid) {
                if (r0 < M) {
                    const float2 rv = *reinterpret_cast<const float2*>(&resid[(size_t)r0 * 256 + col]);
                    v0.x += rv.x; v0.y += rv.y;
                }
                if (r1 < M) {
                    const float2 rv = *reinterpret_cast<const float2*>(&resid[(size_t)r1 * 256 + col]);
                    v1.x += rv.x; v1.y += rv.y;
                }
            }
            if (Ch) {
                if (r0 < M)
                    *reinterpret_cast<__half2*>(&Ch[(size_t)r0 * Ntot + col]) = __floats2half2_rn(v0.x, v0.y);
                if (r1 < M)
                    *reinterpret_cast<__half2*>(&Ch[(size_t)r1 * Ntot + col]) = __floats2half2_rn(v1.x, v1.y);
            } else {
                if (r0 < M) *reinterpret_cast<float2*>(&C[(size_t)r0 * Ntot + col]) = v0;
                if (r1 < M) *reinterpret_cast<float2*>(&C[(size_t)r1 * Ntot + col]) = v1;
            }
        }
    }
}

// ---------------- sampling kernel: 2 queries/block, chunked by qofs --------
__global__ __launch_bounds__(256)
void msda_sample_kernel(const float* __restrict__ rp, int qofs)
{
    const int tid = threadIdx.x;
    const int qi = tid >> 7;
    const int tq = tid & 127;
    const int q = (blockIdx.x + qofs) * 2 + qi;
    const int b = q / NQ;

    __shared__ float s_aw[2][128];
    __shared__ int   s_pos[2][128][4];
    __shared__ float s_wt[2][128][4];

    s_aw[qi][tq] = g_qa[(size_t)q * 384 + 256 + tq];
    __syncthreads();

    if (tid < 16) {
        const int sq = tid >> 3, h = tid & 7;
        float* aw = &s_aw[sq][h * 16];
        float mx = -1e30f;
#pragma unroll
        for (int i = 0; i < 16; i++) mx = fmaxf(mx, aw[i]);
        float e[16];
        float sum = 0.f;
#pragma unroll
        for (int i = 0; i < 16; i++) { e[i] = __expf(aw[i] - mx); sum += e[i]; }
        float inv = 1.f / sum;
#pragma unroll
        for (int i = 0; i < 16; i++) aw[i] = e[i] * inv;
    }
    __syncthreads();

    {
        const int s = tq;
        const int l = (s >> 2) & 3;
        const float aw = s_aw[qi][s];
        const float offx = g_qa[(size_t)q * 384 + s * 2];
        const float offy = g_qa[(size_t)q * 384 + s * 2 + 1];
        const float rx = rp[((size_t)q * LEVELS + l) * 2];
        const float ry = rp[((size_t)q * LEVELS + l) * 2 + 1];
        const int W = c_LW[l], H = c_LH[l], st = c_LS[l];

        const float locx = rx + offx / (float)W;
        const float locy = ry + offy / (float)H;
        const float x = locx * (float)W - 0.5f;
        const float y = locy * (float)H - 0.5f;
        const float x0f = floorf(x), y0f = floorf(y);
        const float lx = x - x0f, ly = y - y0f;
        const int x0 = (int)x0f, y0 = (int)y0f;

#pragma unroll
        for (int cc = 0; cc < 4; cc++) {
            const int dx = cc & 1, dy = cc >> 1;
            const int xi = x0 + dx, yi = y0 + dy;
            const float wx = dx ? lx : (1.f - lx);
            const float wy = dy ? ly : (1.f - ly);
            const bool valid = (xi >= 0) && (xi < W) && (yi >= 0) && (yi < H);
            const int xc = min(max(xi, 0), W - 1);
            const int yc = min(max(yi, 0), H - 1);
            s_pos[qi][s][cc] = st + yc * W + xc;
            s_wt[qi][s][cc] = valid ? (wx * wy * aw) : 0.f;
        }
    }
    __syncthreads();

    const int h = tq >> 4;
    const int d2 = tq & 15;
    const int ch = h * 32 + d2 * 2;
    const __half* vb = g_vh + (size_t)b * NV * EMBED + ch;
    float2 acc = make_float2(0.f, 0.f);
#pragma unroll
    for (int i = 0; i < 16; i++) {
        const int s = h * 16 + i;
#pragma unroll
        for (int cc = 0; cc < 4; cc++) {
            const float w = s_wt[qi][s][cc];
            const __half2 hv = *reinterpret_cast<const __half2*>(vb + (size_t)s_pos[qi][s][cc] * EMBED);
            const float2 f = __half22float2(hv);
            acc.x = fmaf(w, f.x, acc.x);
            acc.y = fmaf(w, f.y, acc.y);
        }
    }
    *reinterpret_cast<float2*>(&g_attn[(size_t)q * EMBED + ch]) = acc;
}

// ---------------- launch ----------------
extern "C" void kernel_launch(void* const* d_in, const int* in_sizes, int n_in,
                              void* d_out, int out_size)
{
    const float* query  = (const float*)d_in[0];
    const float* value  = (const float*)d_in[1];
    const float* rp     = (const float*)d_in[2];
    const float* W_off  = (const float*)d_in[4];
    const float* b_off  = (const float*)d_in[5];
    const float* W_attn = (const float*)d_in[6];
    const float* b_attn = (const float*)d_in[7];
    const float* W_v    = (const float*)d_in[8];
    const float* b_v    = (const float*)d_in[9];
    const float* W_out  = (const float*)d_in[10];
    const float* b_out  = (const float*)d_in[11];
    float* out = (float*)d_out;

    float *pqa, *pattn, *pbias_qa;
    __half* pvh;
    cudaGetSymbolAddress((void**)&pvh,      g_vh);
    cudaGetSymbolAddress((void**)&pqa,      g_qa);
    cudaGetSymbolAddress((void**)&pattn,    g_attn);
    cudaGetSymbolAddress((void**)&pbias_qa, g_bias_qa);

    __half *bvh, *bvl, *bqh, *bql, *buh, *bul;
    cudaGetSymbolAddress((void**)&bvh, g_Bvh); cudaGetSymbolAddress((void**)&bvl, g_Bvl);
    cudaGetSymbolAddress((void**)&bqh, g_Bqh); cudaGetSymbolAddress((void**)&bql, g_Bql);
    cudaGetSymbolAddress((void**)&buh, g_Buh); cudaGetSymbolAddress((void**)&bul, g_Bul);

    const int DS64  = 2 * ((128 + 2 * 64) * ROWB);    // TERMS=2, BN=64
    const int DS128 = 2 * ((128 + 1 * 128) * ROWB);   // TERMS=1, BN=128
    cudaFuncSetAttribute((const void*)mma_gemm_kernel<2, 64, 2>,
                         cudaFuncAttributeMaxDynamicSharedMemorySize, DS64);
    cudaFuncSetAttribute((const void*)mma_gemm_kernel<1, 128, 2>,
                         cudaFuncAttributeMaxDynamicSharedMemorySize, DS128);

    static cudaStream_t s2 = nullptr, s3 = nullptr;
    static cudaEvent_t evFork = nullptr, evQA = nullptr, evS3 = nullptr;
    static cudaEvent_t evV[NCHUNK];
    if (!s2) {
        cudaStreamCreateWithFlags(&s2, cudaStreamNonBlocking);
        cudaStreamCreateWithFlags(&s3, cudaStreamNonBlocking);
        cudaEventCreateWithFlags(&evFork, cudaEventDisableTiming);
        cudaEventCreateWithFlags(&evQA, cudaEventDisableTiming);
        cudaEventCreateWithFlags(&evS3, cudaEventDisableTiming);
        for (int i = 0; i < NCHUNK; i++)
            cudaEventCreateWithFlags(&evV[i], cudaEventDisableTiming);
    }

    // fork: query-path on s2
    cudaEventRecord(evFork, 0);
    cudaStreamWaitEvent(s2, evFork, 0);

    // s2: conv_rest -> fused offsets+logits GEMM
    conv_rest_kernel<<<642, 256, 0, s2>>>(W_off, W_attn, W_out, b_off, b_attn);
    {
        dim3 grid(6, (NBQ + 127) / 128);
        mma_gemm_kernel<2, 64, 2><<<grid, 256, DS64, s2>>>(query, bqh, bql, pbias_qa, nullptr,
                                                           pqa, nullptr, NBQ, 384);
    }
    cudaEventRecord(evQA, s2);

    // main: conv_v then value GEMM in 4 chunks (2 batches each)
    conv_v_kernel<<<256, 256>>>(W_v);
    static const int tb[NCHUNK + 1] = {0, 208, 416, 624, 831};
    for (int i = 0; i < NCHUNK; i++) {
        const int tiles = tb[i + 1] - tb[i];
        const int mloc = MV - tb[i] * 128;              // rows remaining from chunk start
        dim3 grid(2, tiles);
        mma_gemm_kernel<1, 128, 2><<<grid, 256, DS128>>>(
            value + (size_t)tb[i] * 128 * KDIM, bvh, bvl, b_v, nullptr,
            nullptr, pvh + (size_t)tb[i] * 128 * EMBED, mloc, 256);
        cudaEventRecord(evV[i], 0);
    }

    // s3: sampler chunks, each gated on its value chunk (+ qa for chunk 0)
    cudaStreamWaitEvent(s3, evQA, 0);
    for (int i = 0; i < NCHUNK; i++) {
        cudaStreamWaitEvent(s3, evV[i], 0);
        msda_sample_kernel<<<900, 256, 0, s3>>>(rp, i * 900);
    }
    cudaEventRecord(evS3, s3);

    // main: join then output projection + residual
    cudaStreamWaitEvent(0, evS3, 0);
    {
        dim3 grid(4, (NBQ + 127) / 128);
        mma_gemm_kernel<2, 64, 2><<<grid, 256, DS64>>>(pattn, buh, bul, b_out, query,
                                                       out, nullptr, NBQ, 256);
    }
}

// round 16
// speedup vs baseline: 1.0746x; 1.0110x over previous
#include <cuda_runtime.h>
#include <cuda_bf16.h>
#include <cuda_fp16.h>
#include <cstdint>

// ---------------- problem constants ----------------
#define BS      8
#define NQ      900
#define EMBED   256
#define HEADS   8
#define LEVELS  4
#define POINTS  4
#define NV      13294
#define NBQ     (BS * NQ)      // 7200
#define KDIM    256
#define MV      (BS * NV)      // 106352
#define NCHUNK  4
// tile boundaries covering 2 batches per chunk (ceil(i*2*NV/128))
// t = {0, 208, 416, 624, 831}

__device__ __constant__ int c_LH[4] = {100, 50, 25, 13};
__device__ __constant__ int c_LW[4] = {100, 50, 25, 13};
__device__ __constant__ int c_LS[4] = {0, 10000, 12500, 13125};

// ---------------- scratch ----------------
__device__ __half g_vh[(size_t)MV * EMBED];
__device__ float g_qa[(size_t)NBQ * 384];
__device__ float g_attn[(size_t)NBQ * EMBED];
__device__ float g_bias_qa[384];

__device__ __half g_Bvh[256 * 256], g_Bvl[256 * 256];
__device__ __half g_Bqh[384 * 256], g_Bql[384 * 256];
__device__ __half g_Buh[256 * 256], g_Bul[256 * 256];

// ---------------- helpers ----------------
__device__ __forceinline__ uint32_t smem_u32(const void* p) {
    uint32_t a;
    asm("{ .reg .u64 t; cvta.to.shared.u64 t, %1; cvt.u32.u64 %0, t; }" : "=r"(a) : "l"(p));
    return a;
}
__device__ __forceinline__ uint32_t pack_h2(float x, float y) {
    __half2 h = __floats2half2_rn(x, y);
    return *reinterpret_cast<uint32_t*>(&h);
}
__device__ __forceinline__ void mma_f16(float d[4],
                                        uint32_t a0, uint32_t a1, uint32_t a2, uint32_t a3,
                                        uint32_t b0, uint32_t b1) {
    asm volatile(
        "mma.sync.aligned.m16n8k16.row.col.f32.f16.f16.f32 "
        "{%0,%1,%2,%3}, {%4,%5,%6,%7}, {%8,%9}, {%0,%1,%2,%3};"
        : "+f"(d[0]), "+f"(d[1]), "+f"(d[2]), "+f"(d[3])
        : "r"(a0), "r"(a1), "r"(a2), "r"(a3), "r"(b0), "r"(b1));
}
__device__ __forceinline__ void ldsm_x4(uint32_t& r0, uint32_t& r1, uint32_t& r2, uint32_t& r3,
                                        uint32_t addr) {
    asm volatile("ldmatrix.sync.aligned.m8n8.x4.shared.b16 {%0,%1,%2,%3}, [%4];"
                 : "=r"(r0), "=r"(r1), "=r"(r2), "=r"(r3) : "r"(addr));
}
__device__ __forceinline__ void cp_async16(uint32_t saddr, const void* gaddr) {
    asm volatile("cp.async.ca.shared.global [%0], [%1], 16;" :: "r"(saddr), "l"(gaddr));
}

// ---------------- weight conversion kernels ----------------
__device__ __forceinline__ void conv_one(const float* __restrict__ W,
                                         __half* __restrict__ Bh,
                                         __half* __restrict__ Bl,
                                         int N, int j, int nbase) {
    int k = j / N, n = j % N;
    float x = W[j];
    __half hb = __float2half_rn(x);
    float lo = x - __half2float(hb);
    Bh[(size_t)(nbase + n) * KDIM + k] = hb;
    Bl[(size_t)(nbase + n) * KDIM + k] = __float2half_rn(lo);
}

__global__ void conv_v_kernel(const float* __restrict__ Wv) {
    int i = blockIdx.x * 256 + threadIdx.x;
    if (i < 65536) conv_one(Wv, g_Bvh, g_Bvl, 256, i, 0);
}

__global__ void conv_rest_kernel(const float* __restrict__ Woff,
                                 const float* __restrict__ Wattn,
                                 const float* __restrict__ Wout,
                                 const float* __restrict__ b_off,
                                 const float* __restrict__ b_attn) {
    int i = blockIdx.x * 256 + threadIdx.x;
    if (i < 65536)        conv_one(Woff,  g_Bqh, g_Bql, 256, i, 0);
    else if (i < 98304)   conv_one(Wattn, g_Bqh, g_Bql, 128, i - 65536, 256);
    else if (i < 163840)  conv_one(Wout,  g_Buh, g_Bul, 256, i - 98304, 0);
    else if (i < 164224) {
        int j2 = i - 163840;
        g_bias_qa[j2] = (j2 < 256) ? b_off[j2] : b_attn[j2 - 256];
    }
}

// ---------------- HMMA GEMM: CTA 128xBN, fp16 TERMS-split, fp32 A in-kernel -
#define KC 32
#define ROWB 80

template<int TERMS, int BN, int OCC>
__global__ __launch_bounds__(256, OCC)
void mma_gemm_kernel(const float* __restrict__ A,
                     const __half* __restrict__ Bh,
                     const __half* __restrict__ Bl,
                     const float* __restrict__ bias,
                     const float* __restrict__ resid,
                     float* __restrict__ C,
                     __half* __restrict__ Ch,
                     int M, int Ntot)
{
    constexpr int A_B    = 0;
    constexpr int B_HI_B = 128 * ROWB;
    constexpr int B_LO_B = B_HI_B + BN * ROWB;
    constexpr int STAGE  = B_HI_B + TERMS * BN * ROWB;
    constexpr int NTC    = BN / 16;

    extern __shared__ char smemc[];
    __shared__ float s_bias[BN];

    const int tid = threadIdx.x;
    const int wid = tid >> 5;
    const int lane = tid & 31;
    const int g = lane >> 2;
    const int tig = lane & 3;
    const int wm = wid & 3;
    const int wn = wid >> 2;
    const int m0 = blockIdx.y * 128;
    const int n0 = blockIdx.x * BN;

    if (tid < BN) s_bias[tid] = bias[n0 + tid];

    const uint32_t sbase = smem_u32(smemc);

    float acc[2][NTC][4];
#pragma unroll
    for (int mt = 0; mt < 2; mt++)
#pragma unroll
        for (int nt = 0; nt < NTC; nt++)
#pragma unroll
            for (int q = 0; q < 4; q++) acc[mt][nt][q] = 0.f;

    const int a_row[4] = { (tid + 0) >> 3, (tid + 256) >> 3, (tid + 512) >> 3, (tid + 768) >> 3 };
    const int a_q = tid & 7;

    const int lm_arow = lane & 15;
    const int lm_akoff = (lane >> 4) * 16;
    const int lm_brow = (lane & 7) + ((lane >> 4) << 3);
    const int lm_bkoff = ((lane >> 3) & 1) * 16;

    auto fill_A = [&](int stage, const float4* pa) {
#pragma unroll
        for (int i = 0; i < 4; i++) {
            const float4 f = pa[i];
            const uint32_t off = (uint32_t)(a_row[i] * ROWB + a_q * 8);
            *reinterpret_cast<uint2*>(smemc + stage * STAGE + A_B + off) =
                make_uint2(pack_h2(f.x, f.y), pack_h2(f.z, f.w));
        }
    };

    auto issue_B = [&](int stage, int k0) {
        const uint32_t Sb = sbase + stage * STAGE;
#pragma unroll
        for (int u = tid; u < BN * 4; u += 256) {
            const int row = u >> 2, c = u & 3;
            cp_async16(Sb + B_HI_B + row * ROWB + c * 16,
                       Bh + (size_t)(n0 + row) * KDIM + k0 + c * 8);
            if (TERMS == 2)
                cp_async16(Sb + B_LO_B + row * ROWB + c * 16,
                           Bl + (size_t)(n0 + row) * KDIM + k0 + c * 8);
        }
        asm volatile("cp.async.commit_group;" ::: "memory");
    };

    {
        issue_B(0, 0);
        float4 pa[4];
#pragma unroll
        for (int i = 0; i < 4; i++) {
            pa[i] = make_float4(0.f, 0.f, 0.f, 0.f);
            if (m0 + a_row[i] < M)
                pa[i] = *reinterpret_cast<const float4*>(&A[(size_t)(m0 + a_row[i]) * KDIM + a_q * 4]);
        }
        fill_A(0, pa);
        asm volatile("cp.async.wait_group 0;" ::: "memory");
    }
    __syncthreads();

    const int ntiles = KDIM / KC;
    int buf = 0;

    for (int kt = 0; kt < ntiles; kt++) {
        const bool more = (kt + 1 < ntiles);
        float4 pa[4];
        if (more) {
            const int k0 = (kt + 1) * KC;
            issue_B(buf ^ 1, k0);
#pragma unroll
            for (int i = 0; i < 4; i++) {
                pa[i] = make_float4(0.f, 0.f, 0.f, 0.f);
                if (m0 + a_row[i] < M)
                    pa[i] = *reinterpret_cast<const float4*>(&A[(size_t)(m0 + a_row[i]) * KDIM + k0 + a_q * 4]);
            }
        }

        const uint32_t Sb = sbase + buf * STAGE;
#pragma unroll
        for (int kk = 0; kk < 2; kk++) {
            uint32_t bh[NTC][2], bl[NTC][2];
#pragma unroll
            for (int p = 0; p < NTC / 2; p++) {
                const uint32_t baddr = Sb + (uint32_t)((wn * (BN / 2) + p * 16 + lm_brow) * ROWB + kk * 32 + lm_bkoff);
                ldsm_x4(bh[2 * p][0], bh[2 * p][1], bh[2 * p + 1][0], bh[2 * p + 1][1],
                        baddr + B_HI_B);
                if (TERMS == 2)
                    ldsm_x4(bl[2 * p][0], bl[2 * p][1], bl[2 * p + 1][0], bl[2 * p + 1][1],
                            baddr + B_LO_B);
            }
            uint32_t ah[2][4];
#pragma unroll
            for (int mt = 0; mt < 2; mt++) {
                const uint32_t aaddr = Sb + (uint32_t)((wm * 32 + mt * 16 + lm_arow) * ROWB + kk * 32 + lm_akoff);
                ldsm_x4(ah[mt][0], ah[mt][1], ah[mt][2], ah[mt][3], aaddr + A_B);
            }
#pragma unroll
            for (int mt = 0; mt < 2; mt++)
#pragma unroll
                for (int nt = 0; nt < NTC; nt++) {
                    mma_f16(acc[mt][nt], ah[mt][0], ah[mt][1], ah[mt][2], ah[mt][3],
                            bh[nt][0], bh[nt][1]);
                    if (TERMS == 2)
                        mma_f16(acc[mt][nt], ah[mt][0], ah[mt][1], ah[mt][2], ah[mt][3],
                                bl[nt][0], bl[nt][1]);
                }
        }

        if (more) {
            fill_A(buf ^ 1, pa);
            asm volatile("cp.async.wait_group 0;" ::: "memory");
            __syncthreads();
            buf ^= 1;
        }
    }

    // ---- epilogue ----
#pragma unroll
    for (int mt = 0; mt < 2; mt++) {
        const int r0 = m0 + wm * 32 + mt * 16 + g;
        const int r1 = r0 + 8;
#pragma unroll
        for (int nt = 0; nt < NTC; nt++) {
            const int cloc = wn * (BN / 2) + nt * 8 + tig * 2;
            const int col = n0 + cloc;
            const float b0 = s_bias[cloc], b1 = s_bias[cloc + 1];
            float2 v0 = make_float2(acc[mt][nt][0] + b0, acc[mt][nt][1] + b1);
            float2 v1 = make_float2(acc[mt][nt][2] + b0, acc[mt][nt][3] + b1);
            if (resid) {
                if (r0 < M) {
                    const float2 rv = *reinterpret_cast<const float2*>(&resid[(size_t)r0 * 256 + col]);
                    v0.x += rv.x; v0.y += rv.y;
                }
                if (r1 < M) {
                    const float2 rv = *reinterpret_cast<const float2*>(&resid[(size_t)r1 * 256 + col]);
                    v1.x += rv.x; v1.y += rv.y;
                }
            }
            if (Ch) {
                if (r0 < M)
                    *reinterpret_cast<__half2*>(&Ch[(size_t)r0 * Ntot + col]) = __floats2half2_rn(v0.x, v0.y);
                if (r1 < M)
                    *reinterpret_cast<__half2*>(&Ch[(size_t)r1 * Ntot + col]) = __floats2half2_rn(v1.x, v1.y);
            } else {
                if (r0 < M) *reinterpret_cast<float2*>(&C[(size_t)r0 * Ntot + col]) = v0;
                if (r1 < M) *reinterpret_cast<float2*>(&C[(size_t)r1 * Ntot + col]) = v1;
            }
        }
    }
}

// ---------------- sampling kernel: 2 queries/block, chunked by qofs --------
__global__ __launch_bounds__(256)
void msda_sample_kernel(const float* __restrict__ rp, int qofs)
{
    const int tid = threadIdx.x;
    const int qi = tid >> 7;
    const int tq = tid & 127;
    const int q = (blockIdx.x + qofs) * 2 + qi;
    const int b = q / NQ;

    __shared__ float s_aw[2][128];
    __shared__ int   s_pos[2][128][4];
    __shared__ float s_wt[2][128][4];

    s_aw[qi][tq] = g_qa[(size_t)q * 384 + 256 + tq];
    __syncthreads();

    if (tid < 16) {
        const int sq = tid >> 3, h = tid & 7;
        float* aw = &s_aw[sq][h * 16];
        float mx = -1e30f;
#pragma unroll
        for (int i = 0; i < 16; i++) mx = fmaxf(mx, aw[i]);
        float e[16];
        float sum = 0.f;
#pragma unroll
        for (int i = 0; i < 16; i++) { e[i] = __expf(aw[i] - mx); sum += e[i]; }
        float inv = 1.f / sum;
#pragma unroll
        for (int i = 0; i < 16; i++) aw[i] = e[i] * inv;
    }
    __syncthreads();

    {
        const int s = tq;
        const int l = (s >> 2) & 3;
        const float aw = s_aw[qi][s];
        const float offx = g_qa[(size_t)q * 384 + s * 2];
        const float offy = g_qa[(size_t)q * 384 + s * 2 + 1];
        const float rx = rp[((size_t)q * LEVELS + l) * 2];
        const float ry = rp[((size_t)q * LEVELS + l) * 2 + 1];
        const int W = c_LW[l], H = c_LH[l], st = c_LS[l];

        const float locx = rx + offx / (float)W;
        const float locy = ry + offy / (float)H;
        const float x = locx * (float)W - 0.5f;
        const float y = locy * (float)H - 0.5f;
        const float x0f = floorf(x), y0f = floorf(y);
        const float lx = x - x0f, ly = y - y0f;
        const int x0 = (int)x0f, y0 = (int)y0f;

#pragma unroll
        for (int cc = 0; cc < 4; cc++) {
            const int dx = cc & 1, dy = cc >> 1;
            const int xi = x0 + dx, yi = y0 + dy;
            const float wx = dx ? lx : (1.f - lx);
            const float wy = dy ? ly : (1.f - ly);
            const bool valid = (xi >= 0) && (xi < W) && (yi >= 0) && (yi < H);
            const int xc = min(max(xi, 0), W - 1);
            const int yc = min(max(yi, 0), H - 1);
            s_pos[qi][s][cc] = st + yc * W + xc;
            s_wt[qi][s][cc] = valid ? (wx * wy * aw) : 0.f;
        }
    }
    __syncthreads();

    const int h = tq >> 4;
    const int d2 = tq & 15;
    const int ch = h * 32 + d2 * 2;
    const __half* vb = g_vh + (size_t)b * NV * EMBED + ch;
    float2 acc = make_float2(0.f, 0.f);
#pragma unroll
    for (int i = 0; i < 16; i++) {
        const int s = h * 16 + i;
#pragma unroll
        for (int cc = 0; cc < 4; cc++) {
            const float w = s_wt[qi][s][cc];
            const __half2 hv = *reinterpret_cast<const __half2*>(vb + (size_t)s_pos[qi][s][cc] * EMBED);
            const float2 f = __half22float2(hv);
            acc.x = fmaf(w, f.x, acc.x);
            acc.y = fmaf(w, f.y, acc.y);
        }
    }
    *reinterpret_cast<float2*>(&g_attn[(size_t)q * EMBED + ch]) = acc;
}

// ---------------- launch ----------------
extern "C" void kernel_launch(void* const* d_in, const int* in_sizes, int n_in,
                              void* d_out, int out_size)
{
    const float* query  = (const float*)d_in[0];
    const float* value  = (const float*)d_in[1];
    const float* rp     = (const float*)d_in[2];
    const float* W_off  = (const float*)d_in[4];
    const float* b_off  = (const float*)d_in[5];
    const float* W_attn = (const float*)d_in[6];
    const float* b_attn = (const float*)d_in[7];
    const float* W_v    = (const float*)d_in[8];
    const float* b_v    = (const float*)d_in[9];
    const float* W_out  = (const float*)d_in[10];
    const float* b_out  = (const float*)d_in[11];
    float* out = (float*)d_out;

    float *pqa, *pattn, *pbias_qa;
    __half* pvh;
    cudaGetSymbolAddress((void**)&pvh,      g_vh);
    cudaGetSymbolAddress((void**)&pqa,      g_qa);
    cudaGetSymbolAddress((void**)&pattn,    g_attn);
    cudaGetSymbolAddress((void**)&pbias_qa, g_bias_qa);

    __half *bvh, *bvl, *bqh, *bql, *buh, *bul;
    cudaGetSymbolAddress((void**)&bvh, g_Bvh); cudaGetSymbolAddress((void**)&bvl, g_Bvl);
    cudaGetSymbolAddress((void**)&bqh, g_Bqh); cudaGetSymbolAddress((void**)&bql, g_Bql);
    cudaGetSymbolAddress((void**)&buh, g_Buh); cudaGetSymbolAddress((void**)&bul, g_Bul);

    const int DS64  = 2 * ((128 + 2 * 64) * ROWB);    // TERMS=2, BN=64
    const int DS128 = 2 * ((128 + 1 * 128) * ROWB);   // TERMS=1, BN=128
    cudaFuncSetAttribute((const void*)mma_gemm_kernel<2, 64, 2>,
                         cudaFuncAttributeMaxDynamicSharedMemorySize, DS64);
    cudaFuncSetAttribute((const void*)mma_gemm_kernel<1, 128, 2>,
                         cudaFuncAttributeMaxDynamicSharedMemorySize, DS128);

    static cudaStream_t s2 = nullptr, s3 = nullptr;
    static cudaEvent_t evFork = nullptr, evQA = nullptr, evS3 = nullptr;
    static cudaEvent_t evV[NCHUNK];
    if (!s2) {
        cudaStreamCreateWithFlags(&s2, cudaStreamNonBlocking);
        cudaStreamCreateWithFlags(&s3, cudaStreamNonBlocking);
        cudaEventCreateWithFlags(&evFork, cudaEventDisableTiming);
        cudaEventCreateWithFlags(&evQA, cudaEventDisableTiming);
        cudaEventCreateWithFlags(&evS3, cudaEventDisableTiming);
        for (int i = 0; i < NCHUNK; i++)
            cudaEventCreateWithFlags(&evV[i], cudaEventDisableTiming);
    }

    // fork: query-path on s2
    cudaEventRecord(evFork, 0);
    cudaStreamWaitEvent(s2, evFork, 0);

    // s2: conv_rest -> fused offsets+logits GEMM
    conv_rest_kernel<<<642, 256, 0, s2>>>(W_off, W_attn, W_out, b_off, b_attn);
    {
        dim3 grid(6, (NBQ + 127) / 128);
        mma_gemm_kernel<2, 64, 2><<<grid, 256, DS64, s2>>>(query, bqh, bql, pbias_qa, nullptr,
                                                           pqa, nullptr, NBQ, 384);
    }
    cudaEventRecord(evQA, s2);

    // main: conv_v then value GEMM in 4 chunks (2 batches each)
    conv_v_kernel<<<256, 256>>>(W_v);
    static const int tb[NCHUNK + 1] = {0, 208, 416, 624, 831};
    for (int i = 0; i < NCHUNK; i++) {
        const int tiles = tb[i + 1] - tb[i];
        const int mloc = MV - tb[i] * 128;              // rows remaining from chunk start
        dim3 grid(2, tiles);
        mma_gemm_kernel<1, 128, 2><<<grid, 256, DS128>>>(
            value + (size_t)tb[i] * 128 * KDIM, bvh, bvl, b_v, nullptr,
            nullptr, pvh + (size_t)tb[i] * 128 * EMBED, mloc, 256);
        cudaEventRecord(evV[i], 0);
    }

    // s3: sampler chunks, each gated on its value chunk (+ qa for chunk 0)
    cudaStreamWaitEvent(s3, evQA, 0);
    for (int i = 0; i < NCHUNK; i++) {
        cudaStreamWaitEvent(s3, evV[i], 0);
        msda_sample_kernel<<<900, 256, 0, s3>>>(rp, i * 900);
    }
    cudaEventRecord(evS3, s3);

    // main: join then output projection + residual
    cudaStreamWaitEvent(0, evS3, 0);
    {
        dim3 grid(4, (NBQ + 127) / 128);
        mma_gemm_kernel<2, 64, 2><<<grid, 256, DS64>>>(pattn, buh, bul, b_out, query,
                                                       out, nullptr, NBQ, 256);
    }
}

// round 17
// speedup vs baseline: 1.0906x; 1.0149x over previous
#include <cuda_runtime.h>
#include <cuda_bf16.h>
#include <cuda_fp16.h>
#include <cstdint>

// ---------------- problem constants ----------------
#define BS      8
#define NQ      900
#define EMBED   256
#define HEADS   8
#define LEVELS  4
#define POINTS  4
#define NV      13294
#define NBQ     (BS * NQ)      // 7200
#define KDIM    256
#define MV      (BS * NV)      // 106352
#define NCHUNK  4
// tile boundaries covering 2 batches per chunk (ceil(i*2*NV/128))
// t = {0, 208, 416, 624, 831}

__device__ __constant__ int c_LH[4] = {100, 50, 25, 13};
__device__ __constant__ int c_LW[4] = {100, 50, 25, 13};
__device__ __constant__ int c_LS[4] = {0, 10000, 12500, 13125};

// ---------------- scratch ----------------
__device__ __half g_vh[(size_t)MV * EMBED];
__device__ float g_qa[(size_t)NBQ * 384];
__device__ float g_attn[(size_t)NBQ * EMBED];
__device__ float g_bias_qa[384];

__device__ __half g_Bvh[256 * 256], g_Bvl[256 * 256];
__device__ __half g_Bqh[384 * 256], g_Bql[384 * 256];
__device__ __half g_Buh[256 * 256], g_Bul[256 * 256];

// ---------------- helpers ----------------
__device__ __forceinline__ uint32_t smem_u32(const void* p) {
    uint32_t a;
    asm("{ .reg .u64 t; cvta.to.shared.u64 t, %1; cvt.u32.u64 %0, t; }" : "=r"(a) : "l"(p));
    return a;
}
__device__ __forceinline__ uint32_t pack_h2(float x, float y) {
    __half2 h = __floats2half2_rn(x, y);
    return *reinterpret_cast<uint32_t*>(&h);
}
__device__ __forceinline__ void mma_f16(float d[4],
                                        uint32_t a0, uint32_t a1, uint32_t a2, uint32_t a3,
                                        uint32_t b0, uint32_t b1) {
    asm volatile(
        "mma.sync.aligned.m16n8k16.row.col.f32.f16.f16.f32 "
        "{%0,%1,%2,%3}, {%4,%5,%6,%7}, {%8,%9}, {%0,%1,%2,%3};"
        : "+f"(d[0]), "+f"(d[1]), "+f"(d[2]), "+f"(d[3])
        : "r"(a0), "r"(a1), "r"(a2), "r"(a3), "r"(b0), "r"(b1));
}
__device__ __forceinline__ void ldsm_x4(uint32_t& r0, uint32_t& r1, uint32_t& r2, uint32_t& r3,
                                        uint32_t addr) {
    asm volatile("ldmatrix.sync.aligned.m8n8.x4.shared.b16 {%0,%1,%2,%3}, [%4];"
                 : "=r"(r0), "=r"(r1), "=r"(r2), "=r"(r3) : "r"(addr));
}
__device__ __forceinline__ void cp_async16(uint32_t saddr, const void* gaddr) {
    asm volatile("cp.async.ca.shared.global [%0], [%1], 16;" :: "r"(saddr), "l"(gaddr));
}

// ---------------- weight conversion kernels ----------------
__device__ __forceinline__ void conv_one(const float* __restrict__ W,
                                         __half* __restrict__ Bh,
                                         __half* __restrict__ Bl,
                                         int N, int j, int nbase) {
    int k = j / N, n = j % N;
    float x = W[j];
    __half hb = __float2half_rn(x);
    float lo = x - __half2float(hb);
    Bh[(size_t)(nbase + n) * KDIM + k] = hb;
    Bl[(size_t)(nbase + n) * KDIM + k] = __float2half_rn(lo);
}

__global__ void conv_v_kernel(const float* __restrict__ Wv) {
    int i = blockIdx.x * 256 + threadIdx.x;
    if (i < 65536) conv_one(Wv, g_Bvh, g_Bvl, 256, i, 0);
}

__global__ void conv_rest_kernel(const float* __restrict__ Woff,
                                 const float* __restrict__ Wattn,
                                 const float* __restrict__ Wout,
                                 const float* __restrict__ b_off,
                                 const float* __restrict__ b_attn) {
    int i = blockIdx.x * 256 + threadIdx.x;
    if (i < 65536)        conv_one(Woff,  g_Bqh, g_Bql, 256, i, 0);
    else if (i < 98304)   conv_one(Wattn, g_Bqh, g_Bql, 128, i - 65536, 256);
    else if (i < 163840)  conv_one(Wout,  g_Buh, g_Bul, 256, i - 98304, 0);
    else if (i < 164224) {
        int j2 = i - 163840;
        g_bias_qa[j2] = (j2 < 256) ? b_off[j2] : b_attn[j2 - 256];
    }
}

// ---------------- HMMA GEMM: CTA 128xBN, fp16 TERMS-split, fp32 A in-kernel -
#define KC 32
#define ROWB 80

template<int TERMS, int BN, int OCC>
__global__ __launch_bounds__(256, OCC)
void mma_gemm_kernel(const float* __restrict__ A,
                     const __half* __restrict__ Bh,
                     const __half* __restrict__ Bl,
                     const float* __restrict__ bias,
                     const float* __restrict__ resid,
                     float* __restrict__ C,
                     __half* __restrict__ Ch,
                     int M, int Ntot)
{
    constexpr int A_B    = 0;
    constexpr int B_HI_B = 128 * ROWB;
    constexpr int B_LO_B = B_HI_B + BN * ROWB;
    constexpr int STAGE  = B_HI_B + TERMS * BN * ROWB;
    constexpr int NTC    = BN / 16;

    extern __shared__ char smemc[];
    __shared__ float s_bias[BN];

    const int tid = threadIdx.x;
    const int wid = tid >> 5;
    const int lane = tid & 31;
    const int g = lane >> 2;
    const int tig = lane & 3;
    const int wm = wid & 3;
    const int wn = wid >> 2;
    const int m0 = blockIdx.y * 128;
    const int n0 = blockIdx.x * BN;

    if (tid < BN) s_bias[tid] = bias[n0 + tid];

    const uint32_t sbase = smem_u32(smemc);

    float acc[2][NTC][4];
#pragma unroll
    for (int mt = 0; mt < 2; mt++)
#pragma unroll
        for (int nt = 0; nt < NTC; nt++)
#pragma unroll
            for (int q = 0; q < 4; q++) acc[mt][nt][q] = 0.f;

    const int a_row[4] = { (tid + 0) >> 3, (tid + 256) >> 3, (tid + 512) >> 3, (tid + 768) >> 3 };
    const int a_q = tid & 7;

    const int lm_arow = lane & 15;
    const int lm_akoff = (lane >> 4) * 16;
    const int lm_brow = (lane & 7) + ((lane >> 4) << 3);
    const int lm_bkoff = ((lane >> 3) & 1) * 16;

    auto fill_A = [&](int stage, const float4* pa) {
#pragma unroll
        for (int i = 0; i < 4; i++) {
            const float4 f = pa[i];
            const uint32_t off = (uint32_t)(a_row[i] * ROWB + a_q * 8);
            *reinterpret_cast<uint2*>(smemc + stage * STAGE + A_B + off) =
                make_uint2(pack_h2(f.x, f.y), pack_h2(f.z, f.w));
        }
    };

    auto issue_B = [&](int stage, int k0) {
        const uint32_t Sb = sbase + stage * STAGE;
#pragma unroll
        for (int u = tid; u < BN * 4; u += 256) {
            const int row = u >> 2, c = u & 3;
            cp_async16(Sb + B_HI_B + row * ROWB + c * 16,
                       Bh + (size_t)(n0 + row) * KDIM + k0 + c * 8);
            if (TERMS == 2)
                cp_async16(Sb + B_LO_B + row * ROWB + c * 16,
                           Bl + (size_t)(n0 + row) * KDIM + k0 + c * 8);
        }
        asm volatile("cp.async.commit_group;" ::: "memory");
    };

    {
        issue_B(0, 0);
        float4 pa[4];
#pragma unroll
        for (int i = 0; i < 4; i++) {
            pa[i] = make_float4(0.f, 0.f, 0.f, 0.f);
            if (m0 + a_row[i] < M)
                pa[i] = *reinterpret_cast<const float4*>(&A[(size_t)(m0 + a_row[i]) * KDIM + a_q * 4]);
        }
        fill_A(0, pa);
        asm volatile("cp.async.wait_group 0;" ::: "memory");
    }
    __syncthreads();

    const int ntiles = KDIM / KC;
    int buf = 0;

    for (int kt = 0; kt < ntiles; kt++) {
        const bool more = (kt + 1 < ntiles);
        float4 pa[4];
        if (more) {
            const int k0 = (kt + 1) * KC;
            issue_B(buf ^ 1, k0);
#pragma unroll
            for (int i = 0; i < 4; i++) {
                pa[i] = make_float4(0.f, 0.f, 0.f, 0.f);
                if (m0 + a_row[i] < M)
                    pa[i] = *reinterpret_cast<const float4*>(&A[(size_t)(m0 + a_row[i]) * KDIM + k0 + a_q * 4]);
            }
        }

        const uint32_t Sb = sbase + buf * STAGE;
#pragma unroll
        for (int kk = 0; kk < 2; kk++) {
            uint32_t bh[NTC][2], bl[NTC][2];
#pragma unroll
            for (int p = 0; p < NTC / 2; p++) {
                const uint32_t baddr = Sb + (uint32_t)((wn * (BN / 2) + p * 16 + lm_brow) * ROWB + kk * 32 + lm_bkoff);
                ldsm_x4(bh[2 * p][0], bh[2 * p][1], bh[2 * p + 1][0], bh[2 * p + 1][1],
                        baddr + B_HI_B);
                if (TERMS == 2)
                    ldsm_x4(bl[2 * p][0], bl[2 * p][1], bl[2 * p + 1][0], bl[2 * p + 1][1],
                            baddr + B_LO_B);
            }
            uint32_t ah[2][4];
#pragma unroll
            for (int mt = 0; mt < 2; mt++) {
                const uint32_t aaddr = Sb + (uint32_t)((wm * 32 + mt * 16 + lm_arow) * ROWB + kk * 32 + lm_akoff);
                ldsm_x4(ah[mt][0], ah[mt][1], ah[mt][2], ah[mt][3], aaddr + A_B);
            }
#pragma unroll
            for (int mt = 0; mt < 2; mt++)
#pragma unroll
                for (int nt = 0; nt < NTC; nt++) {
                    mma_f16(acc[mt][nt], ah[mt][0], ah[mt][1], ah[mt][2], ah[mt][3],
                            bh[nt][0], bh[nt][1]);
                    if (TERMS == 2)
                        mma_f16(acc[mt][nt], ah[mt][0], ah[mt][1], ah[mt][2], ah[mt][3],
                                bl[nt][0], bl[nt][1]);
                }
        }

        if (more) {
            fill_A(buf ^ 1, pa);
            asm volatile("cp.async.wait_group 0;" ::: "memory");
            __syncthreads();
            buf ^= 1;
        }
    }

    // ---- epilogue ----
#pragma unroll
    for (int mt = 0; mt < 2; mt++) {
        const int r0 = m0 + wm * 32 + mt * 16 + g;
        const int r1 = r0 + 8;
#pragma unroll
        for (int nt = 0; nt < NTC; nt++) {
            const int cloc = wn * (BN / 2) + nt * 8 + tig * 2;
            const int col = n0 + cloc;
            const float b0 = s_bias[cloc], b1 = s_bias[cloc + 1];
            float2 v0 = make_float2(acc[mt][nt][0] + b0, acc[mt][nt][1] + b1);
            float2 v1 = make_float2(acc[mt][nt][2] + b0, acc[mt][nt][3] + b1);
            if (resid) {
                if (r0 < M) {
                    const float2 rv = *reinterpret_cast<const float2*>(&resid[(size_t)r0 * 256 + col]);
                    v0.x += rv.x; v0.y += rv.y;
                }
                if (r1 < M) {
                    const float2 rv = *reinterpret_cast<const float2*>(&resid[(size_t)r1 * 256 + col]);
                    v1.x += rv.x; v1.y += rv.y;
                }
            }
            if (Ch) {
                if (r0 < M)
                    *reinterpret_cast<__half2*>(&Ch[(size_t)r0 * Ntot + col]) = __floats2half2_rn(v0.x, v0.y);
                if (r1 < M)
                    *reinterpret_cast<__half2*>(&Ch[(size_t)r1 * Ntot + col]) = __floats2half2_rn(v1.x, v1.y);
            } else {
                if (r0 < M) *reinterpret_cast<float2*>(&C[(size_t)r0 * Ntot + col]) = v0;
                if (r1 < M) *reinterpret_cast<float2*>(&C[(size_t)r1 * Ntot + col]) = v1;
            }
        }
    }
}

// ---------------- sampling kernel: 2 queries/block, chunked by qofs --------
__global__ __launch_bounds__(256)
void msda_sample_kernel(const float* __restrict__ rp, int qofs)
{
    const int tid = threadIdx.x;
    const int qi = tid >> 7;
    const int tq = tid & 127;
    const int q = (blockIdx.x + qofs) * 2 + qi;
    const int b = q / NQ;

    __shared__ float s_aw[2][128];
    __shared__ int   s_pos[2][128][4];
    __shared__ float s_wt[2][128][4];

    s_aw[qi][tq] = g_qa[(size_t)q * 384 + 256 + tq];
    __syncthreads();

    if (tid < 16) {
        const int sq = tid >> 3, h = tid & 7;
        float* aw = &s_aw[sq][h * 16];
        float mx = -1e30f;
#pragma unroll
        for (int i = 0; i < 16; i++) mx = fmaxf(mx, aw[i]);
        float e[16];
        float sum = 0.f;
#pragma unroll
        for (int i = 0; i < 16; i++) { e[i] = __expf(aw[i] - mx); sum += e[i]; }
        float inv = 1.f / sum;
#pragma unroll
        for (int i = 0; i < 16; i++) aw[i] = e[i] * inv;
    }
    __syncthreads();

    {
        const int s = tq;
        const int l = (s >> 2) & 3;
        const float aw = s_aw[qi][s];
        const float offx = g_qa[(size_t)q * 384 + s * 2];
        const float offy = g_qa[(size_t)q * 384 + s * 2 + 1];
        const float rx = rp[((size_t)q * LEVELS + l) * 2];
        const float ry = rp[((size_t)q * LEVELS + l) * 2 + 1];
        const int W = c_LW[l], H = c_LH[l], st = c_LS[l];

        const float locx = rx + offx / (float)W;
        const float locy = ry + offy / (float)H;
        const float x = locx * (float)W - 0.5f;
        const float y = locy * (float)H - 0.5f;
        const float x0f = floorf(x), y0f = floorf(y);
        const float lx = x - x0f, ly = y - y0f;
        const int x0 = (int)x0f, y0 = (int)y0f;

#pragma unroll
        for (int cc = 0; cc < 4; cc++) {
            const int dx = cc & 1, dy = cc >> 1;
            const int xi = x0 + dx, yi = y0 + dy;
            const float wx = dx ? lx : (1.f - lx);
            const float wy = dy ? ly : (1.f - ly);
            const bool valid = (xi >= 0) && (xi < W) && (yi >= 0) && (yi < H);
            const int xc = min(max(xi, 0), W - 1);
            const int yc = min(max(yi, 0), H - 1);
            s_pos[qi][s][cc] = st + yc * W + xc;
            s_wt[qi][s][cc] = valid ? (wx * wy * aw) : 0.f;
        }
    }
    __syncthreads();

    const int h = tq >> 4;
    const int d2 = tq & 15;
    const int ch = h * 32 + d2 * 2;
    const __half* vb = g_vh + (size_t)b * NV * EMBED + ch;
    float2 acc = make_float2(0.f, 0.f);
#pragma unroll
    for (int i = 0; i < 16; i++) {
        const int s = h * 16 + i;
#pragma unroll
        for (int cc = 0; cc < 4; cc++) {
            const float w = s_wt[qi][s][cc];
            const __half2 hv = *reinterpret_cast<const __half2*>(vb + (size_t)s_pos[qi][s][cc] * EMBED);
            const float2 f = __half22float2(hv);
            acc.x = fmaf(w, f.x, acc.x);
            acc.y = fmaf(w, f.y, acc.y);
        }
    }
    *reinterpret_cast<float2*>(&g_attn[(size_t)q * EMBED + ch]) = acc;
}

// ---------------- launch ----------------
extern "C" void kernel_launch(void* const* d_in, const int* in_sizes, int n_in,
                              void* d_out, int out_size)
{
    const float* query  = (const float*)d_in[0];
    const float* value  = (const float*)d_in[1];
    const float* rp     = (const float*)d_in[2];
    const float* W_off  = (const float*)d_in[4];
    const float* b_off  = (const float*)d_in[5];
    const float* W_attn = (const float*)d_in[6];
    const float* b_attn = (const float*)d_in[7];
    const float* W_v    = (const float*)d_in[8];
    const float* b_v    = (const float*)d_in[9];
    const float* W_out  = (const float*)d_in[10];
    const float* b_out  = (const float*)d_in[11];
    float* out = (float*)d_out;

    float *pqa, *pattn, *pbias_qa;
    __half* pvh;
    cudaGetSymbolAddress((void**)&pvh,      g_vh);
    cudaGetSymbolAddress((void**)&pqa,      g_qa);
    cudaGetSymbolAddress((void**)&pattn,    g_attn);
    cudaGetSymbolAddress((void**)&pbias_qa, g_bias_qa);

    __half *bvh, *bvl, *bqh, *bql, *buh, *bul;
    cudaGetSymbolAddress((void**)&bvh, g_Bvh); cudaGetSymbolAddress((void**)&bvl, g_Bvl);
    cudaGetSymbolAddress((void**)&bqh, g_Bqh); cudaGetSymbolAddress((void**)&bql, g_Bql);
    cudaGetSymbolAddress((void**)&buh, g_Buh); cudaGetSymbolAddress((void**)&bul, g_Bul);

    const int DS64  = 2 * ((128 + 2 * 64) * ROWB);    // TERMS=2, BN=64
    const int DS128 = 2 * ((128 + 1 * 128) * ROWB);   // TERMS=1, BN=128
    cudaFuncSetAttribute((const void*)mma_gemm_kernel<2, 64, 2>,
                         cudaFuncAttributeMaxDynamicSharedMemorySize, DS64);
    cudaFuncSetAttribute((const void*)mma_gemm_kernel<1, 128, 2>,
                         cudaFuncAttributeMaxDynamicSharedMemorySize, DS128);

    static cudaStream_t s2 = nullptr, s3 = nullptr;
    static cudaEvent_t evFork = nullptr, evQA = nullptr, evS3 = nullptr;
    static cudaEvent_t evV[NCHUNK];
    if (!s2) {
        cudaStreamCreateWithFlags(&s2, cudaStreamNonBlocking);
        cudaStreamCreateWithFlags(&s3, cudaStreamNonBlocking);
        cudaEventCreateWithFlags(&evFork, cudaEventDisableTiming);
        cudaEventCreateWithFlags(&evQA, cudaEventDisableTiming);
        cudaEventCreateWithFlags(&evS3, cudaEventDisableTiming);
        for (int i = 0; i < NCHUNK; i++)
            cudaEventCreateWithFlags(&evV[i], cudaEventDisableTiming);
    }

    // fork: query-path on s2
    cudaEventRecord(evFork, 0);
    cudaStreamWaitEvent(s2, evFork, 0);

    // s2: conv_rest -> fused offsets+logits GEMM
    conv_rest_kernel<<<642, 256, 0, s2>>>(W_off, W_attn, W_out, b_off, b_attn);
    {
        dim3 grid(6, (NBQ + 127) / 128);
        mma_gemm_kernel<2, 64, 2><<<grid, 256, DS64, s2>>>(query, bqh, bql, pbias_qa, nullptr,
                                                           pqa, nullptr, NBQ, 384);
    }
    cudaEventRecord(evQA, s2);

    // main: conv_v then value GEMM in 4 chunks (2 batches each)
    conv_v_kernel<<<256, 256>>>(W_v);
    static const int tb[NCHUNK + 1] = {0, 208, 416, 624, 831};
    for (int i = 0; i < NCHUNK; i++) {
        const int tiles = tb[i + 1] - tb[i];
        const int mloc = MV - tb[i] * 128;              // rows remaining from chunk start
        dim3 grid(2, tiles);
        mma_gemm_kernel<1, 128, 2><<<grid, 256, DS128>>>(
            value + (size_t)tb[i] * 128 * KDIM, bvh, bvl, b_v, nullptr,
            nullptr, pvh + (size_t)tb[i] * 128 * EMBED, mloc, 256);
        cudaEventRecord(evV[i], 0);
    }

    // s3: sampler chunks, each gated on its value chunk (+ qa for chunk 0)
    cudaStreamWaitEvent(s3, evQA, 0);
    for (int i = 0; i < NCHUNK; i++) {
        cudaStreamWaitEvent(s3, evV[i], 0);
        msda_sample_kernel<<<900, 256, 0, s3>>>(rp, i * 900);
    }
    cudaEventRecord(evS3, s3);

    // main: join then output projection + residual
    cudaStreamWaitEvent(0, evS3, 0);
    {
        dim3 grid(4, (NBQ + 127) / 128);
        mma_gemm_kernel<2, 64, 2><<<grid, 256, DS64>>>(pattn, buh, bul, b_out, query,
                                                       out, nullptr, NBQ, 256);
    }
}